// round 2
// baseline (speedup 1.0000x reference)
#include <cuda_runtime.h>
#include <math.h>

#define L 16
#define C 128
#define HH 96
#define WW 96
#define HW (HH*WW)          // 9216
#define CHW (C*HW)          // 1179648

// ---------------- scratch (device globals; no allocation allowed) ----------------
__device__ float g_weff[C*25];     // [c][k] folded conv weights
__device__ float g_beta[25];       // per-tap bias contribution
__device__ float g_WvT[C*C];       // WvT[k][c] = Wv[c][k]
__device__ float g_Ak[L*HW];       // [j][hw]
__device__ float g_wsm[L*HW];      // softmax weights [j][hw]
__device__ float g_xbar[C*HW];     // weighted frame average [c][hw]

// ---------------- 1. fold Wk,bk into 5x5 attention weights ----------------
// weff[c][k] = sum_d Wa[C+d][k] * Wk[d][c];  beta[k] = sum_d Wa[C+d][k] * bk[d]
__global__ void fold_kernel(const float* __restrict__ Wk,
                            const float* __restrict__ bk,
                            const float* __restrict__ Wa) {
    int k = blockIdx.x;      // 0..24
    int c = threadIdx.x;     // 0..127
    float acc = 0.f;
    for (int d = 0; d < C; d++) {
        acc += Wa[(C + d) * 25 + k] * Wk[d * C + c];
    }
    g_weff[c * 25 + k] = acc;
    if (c == 0) {
        float b = 0.f;
        for (int d = 0; d < C; d++) b += Wa[(C + d) * 25 + k] * bk[d];
        g_beta[k] = b;
    }
}

// ---------------- 2. transpose Wv for coalesced GEMM staging ----------------
__global__ void transpose_wv(const float* __restrict__ Wv) {
    int k = blockIdx.x;      // 0..127
    int c = threadIdx.x;     // 0..127
    g_WvT[k * C + c] = Wv[c * C + k];
}

// ---------------- 3. Ak = direct C->1 5x5 conv on x (folded) ----------------
// grid (3,3,16), block (8,32). Tile 32x32 output, thread computes 4 outputs in a row.
__global__ void conv_ak_kernel(const float* __restrict__ x) {
    const int l   = blockIdx.z;
    const int ty0 = blockIdx.y * 32;
    const int tx0 = blockIdx.x * 32;
    __shared__ float xs[36 * 36];
    __shared__ float wks[25];
    __shared__ float betas[32];

    const int tid = threadIdx.y * 8 + threadIdx.x;   // 0..255
    const int row = threadIdx.y;                     // 0..31
    const int c0  = threadIdx.x * 4;                 // 0..28

    if (tid < 25) betas[tid] = g_beta[tid];

    float acc0 = 0.f, acc1 = 0.f, acc2 = 0.f, acc3 = 0.f;

    const float* xl = x + (size_t)l * CHW;

    for (int c = 0; c < C; c++) {
        // stage folded weights for this channel
        if (tid < 25) wks[tid] = g_weff[c * 25 + tid];
        // stage 36x36 zero-padded patch
        const float* xc = xl + c * HW;
        #pragma unroll
        for (int i = tid; i < 1296; i += 256) {
            int r  = i / 36;
            int cc = i - r * 36;
            int gh = ty0 + r - 2;
            int gw = tx0 + cc - 2;
            float v = 0.f;
            if (gh >= 0 && gh < HH && gw >= 0 && gw < WW) v = xc[gh * WW + gw];
            xs[i] = v;
        }
        __syncthreads();

        #pragma unroll
        for (int kh = 0; kh < 5; kh++) {
            const float4 a = *(const float4*)&xs[(row + kh) * 36 + c0];
            const float4 b = *(const float4*)&xs[(row + kh) * 36 + c0 + 4];
            float v0 = a.x, v1 = a.y, v2 = a.z, v3 = a.w;
            float v4 = b.x, v5 = b.y, v6 = b.z, v7 = b.w;
            float w0 = wks[kh * 5 + 0], w1 = wks[kh * 5 + 1], w2 = wks[kh * 5 + 2];
            float w3 = wks[kh * 5 + 3], w4 = wks[kh * 5 + 4];
            acc0 += w0 * v0 + w1 * v1 + w2 * v2 + w3 * v3 + w4 * v4;
            acc1 += w0 * v1 + w1 * v2 + w2 * v3 + w3 * v4 + w4 * v5;
            acc2 += w0 * v2 + w1 * v3 + w2 * v4 + w3 * v5 + w4 * v6;
            acc3 += w0 * v3 + w1 * v4 + w2 * v5 + w3 * v6 + w4 * v7;
        }
        __syncthreads();
    }

    // border-aware bias (conv of bk-constant with zero padding) + store
    const int h = ty0 + row;
    float accs[4] = {acc0, acc1, acc2, acc3};
    #pragma unroll
    for (int p = 0; p < 4; p++) {
        int w = tx0 + c0 + p;
        float bias = 0.f;
        #pragma unroll
        for (int kh = 0; kh < 5; kh++) {
            int hh = h + kh - 2;
            if (hh < 0 || hh >= HH) continue;
            #pragma unroll
            for (int kw = 0; kw < 5; kw++) {
                int ww = w + kw - 2;
                if (ww >= 0 && ww < WW) bias += betas[kh * 5 + kw];
            }
        }
        g_Ak[l * HW + h * WW + w] = accs[p] + bias;
    }
}

// ---------------- 4. softmax over frames j for each pixel ----------------
__global__ void softmax_kernel() {
    int hw = blockIdx.x * 256 + threadIdx.x;   // 36*256 = 9216 exact
    float a[L];
    float mx = -1e30f;
    #pragma unroll
    for (int j = 0; j < L; j++) {
        a[j] = g_Ak[j * HW + hw];
        mx = fmaxf(mx, a[j]);
    }
    float s = 0.f;
    #pragma unroll
    for (int j = 0; j < L; j++) {
        a[j] = __expf(a[j] - mx);
        s += a[j];
    }
    float inv = 1.f / s;
    #pragma unroll
    for (int j = 0; j < L; j++) g_wsm[j * HW + hw] = a[j] * inv;
}

// ---------------- 5. xbar[c][hw] = sum_j w[j][hw] * x[j][c][hw] ----------------
// grid (36, 32), block 256. Each thread: one hw, 4 channels.
__global__ void xbar_kernel(const float* __restrict__ x) {
    int hw = blockIdx.x * 256 + threadIdx.x;
    int cbase = blockIdx.y * 4;
    float w[L];
    #pragma unroll
    for (int j = 0; j < L; j++) w[j] = g_wsm[j * HW + hw];
    #pragma unroll
    for (int i = 0; i < 4; i++) {
        int c = cbase + i;
        float acc = 0.f;
        #pragma unroll
        for (int j = 0; j < L; j++)
            acc += w[j] * x[(size_t)(j * C + c) * HW + hw];
        g_xbar[c * HW + hw] = acc;
    }
}

// ---------------- 6. out[f][c][hw] = Wv . xbar + bv, broadcast to 16 frames ----
// grid (144, 2), block (16,16). Tile 64c x 64p, thread tile 4x4.
__global__ void gemm_out_kernel(const float* __restrict__ bv,
                                float* __restrict__ out) {
    __shared__ float wv_s[16][64];
    __shared__ float xb_s[16][64];
    const int tid = threadIdx.y * 16 + threadIdx.x;
    const int pG = blockIdx.x * 64;
    const int cG = blockIdx.y * 64;

    float acc[4][4];
    #pragma unroll
    for (int i = 0; i < 4; i++)
        #pragma unroll
        for (int j = 0; j < 4; j++) acc[i][j] = 0.f;

    for (int k0 = 0; k0 < C; k0 += 16) {
        #pragma unroll
        for (int i = tid; i < 1024; i += 256) {
            int r = i >> 6, col = i & 63;
            wv_s[r][col] = g_WvT[(k0 + r) * C + cG + col];
            xb_s[r][col] = g_xbar[(k0 + r) * HW + pG + col];
        }
        __syncthreads();
        #pragma unroll
        for (int kk = 0; kk < 16; kk++) {
            const float4 wv4 = *(const float4*)&wv_s[kk][threadIdx.y * 4];
            const float4 xb4 = *(const float4*)&xb_s[kk][threadIdx.x * 4];
            float wr[4] = {wv4.x, wv4.y, wv4.z, wv4.w};
            float xr[4] = {xb4.x, xb4.y, xb4.z, xb4.w};
            #pragma unroll
            for (int ci = 0; ci < 4; ci++)
                #pragma unroll
                for (int pi = 0; pi < 4; pi++)
                    acc[ci][pi] += wr[ci] * xr[pi];
        }
        __syncthreads();
    }

    const int c0 = cG + threadIdx.y * 4;
    const int p0 = pG + threadIdx.x * 4;
    #pragma unroll
    for (int ci = 0; ci < 4; ci++) {
        float b = bv[c0 + ci];
        float4 v = make_float4(acc[ci][0] + b, acc[ci][1] + b,
                               acc[ci][2] + b, acc[ci][3] + b);
        #pragma unroll
        for (int f = 0; f < L; f++) {
            *(float4*)&out[(size_t)(f * C + c0 + ci) * HW + p0] = v;
        }
    }
}

// ---------------- launch ----------------
extern "C" void kernel_launch(void* const* d_in, const int* in_sizes, int n_in,
                              void* d_out, int out_size) {
    const float* x  = (const float*)d_in[0];
    // d_in[1]=Wq, d_in[2]=bq are provably unused (cancel in softmax over j)
    const float* Wk = (const float*)d_in[3];
    const float* bk = (const float*)d_in[4];
    const float* Wv = (const float*)d_in[5];
    const float* bv = (const float*)d_in[6];
    const float* Wa = (const float*)d_in[7];
    float* out = (float*)d_out;

    fold_kernel<<<25, 128>>>(Wk, bk, Wa);
    transpose_wv<<<C, C>>>(Wv);
    conv_ak_kernel<<<dim3(3, 3, L), dim3(8, 32)>>>(x);
    softmax_kernel<<<36, 256>>>();
    xbar_kernel<<<dim3(36, 32), 256>>>(x);
    gemm_out_kernel<<<dim3(HW / 64, 2), dim3(16, 16)>>>(bv, out);
}

// round 3
// speedup vs baseline: 2.4113x; 2.4113x over previous
#include <cuda_runtime.h>
#include <math.h>

#define L 16
#define C 128
#define HH 96
#define WW 96
#define HW (HH*WW)          // 9216
#define CHW (C*HW)          // 1179648

// ---------------- scratch (device globals; no runtime allocation) -------------
__device__ float2 g_weff2[C*25];       // [c][k] folded conv weights, duplicated {w,w}
__device__ float  g_WvT[C*C];          // WvT[k][c] = Wv[c][k]
__device__ float  g_t[25*L*HW];        // rank-25 projection [l][k][hw]  (14.7 MB)
__device__ float  g_wsm[L*HW];         // softmax weights [j][hw]
__device__ float  g_xbar[C*HW];        // weighted frame average [c][hw]

// ---------------- 1. fold Wk into the 25 per-tap projection vectors ----------
// weff[c][k] = sum_d Wa[C+d][k] * Wk[d][c]   (bk/ba/Wq/bq all cancel in softmax)
__global__ void fold_kernel(const float* __restrict__ Wk,
                            const float* __restrict__ Wa) {
    int k = blockIdx.x;      // 0..24
    int c = threadIdx.x;     // 0..127
    float acc = 0.f;
    #pragma unroll 4
    for (int d = 0; d < C; d++)
        acc += Wa[(C + d) * 25 + k] * Wk[d * C + c];
    g_weff2[c * 25 + k] = make_float2(acc, acc);
}

// ---------------- 2. transpose Wv -------------------------------------------
__global__ void transpose_wv(const float* __restrict__ Wv) {
    int k = blockIdx.x;
    int c = threadIdx.x;
    g_WvT[k * C + c] = Wv[c * C + k];
}

// ---------------- 3. t[l][k][hw] = sum_c weff[c][k] * x[l][c][hw] ------------
// grid (18, L), block 256. Each thread owns hw0 and hw0+256; the pair is packed
// into f32x2 so every tap costs one FFMA2. Weights broadcast from smem (LDS.64).
__global__ void proj_kernel(const float* __restrict__ x) {
    __shared__ unsigned long long ws2[C * 25];   // duplicated weights, 25.6 KB
    const int tid = threadIdx.x;
    const int l   = blockIdx.y;
    const int hw0 = blockIdx.x * 512 + tid;

    const unsigned long long* wsrc = (const unsigned long long*)g_weff2;
    #pragma unroll
    for (int i = tid; i < C * 25; i += 256) ws2[i] = wsrc[i];
    __syncthreads();

    unsigned long long acc[25];
    #pragma unroll
    for (int k = 0; k < 25; k++) acc[k] = 0ull;   // {0.f, 0.f}

    const float* xl = x + (size_t)l * CHW + hw0;
    #pragma unroll 2
    for (int c = 0; c < C; c++) {
        float a = xl[c * HW];
        float b = xl[c * HW + 256];
        unsigned long long av;
        asm("mov.b64 %0, {%1, %2};" : "=l"(av) : "f"(a), "f"(b));
        const unsigned long long* wc = &ws2[c * 25];
        #pragma unroll
        for (int k = 0; k < 25; k++)
            asm("fma.rn.f32x2 %0, %1, %2, %0;" : "+l"(acc[k]) : "l"(wc[k]), "l"(av));
    }

    float* tl = g_t + (size_t)l * 25 * HW + hw0;
    #pragma unroll
    for (int k = 0; k < 25; k++) {
        float lo, hi;
        asm("mov.b64 {%0, %1}, %2;" : "=f"(lo), "=f"(hi) : "l"(acc[k]));
        tl[k * HW]       = lo;
        tl[k * HW + 256] = hi;
    }
}

// ---------------- 4. Ak = 25-tap shifted sum of t, then softmax over j -------
// t (14.7 MB) is L2-resident. One thread per pixel; 16 frames in registers.
__global__ void attn_weights_kernel() {
    const int hw = blockIdx.x * 256 + threadIdx.x;
    const int h  = hw / WW;
    const int w  = hw - h * WW;

    float a[L];
    #pragma unroll
    for (int l = 0; l < L; l++) a[l] = 0.f;

    #pragma unroll
    for (int kh = 0; kh < 5; kh++) {
        const int hh = h + kh - 2;
        if ((unsigned)hh >= HH) continue;
        #pragma unroll
        for (int kw = 0; kw < 5; kw++) {
            const int ww = w + kw - 2;
            if ((unsigned)ww >= WW) continue;
            const float* tp = g_t + (size_t)(kh * 5 + kw) * HW + hh * WW + ww;
            #pragma unroll
            for (int l = 0; l < L; l++)
                a[l] += tp[(size_t)l * 25 * HW];
        }
    }

    float mx = a[0];
    #pragma unroll
    for (int l = 1; l < L; l++) mx = fmaxf(mx, a[l]);
    float s = 0.f;
    #pragma unroll
    for (int l = 0; l < L; l++) { a[l] = __expf(a[l] - mx); s += a[l]; }
    float inv = 1.f / s;
    #pragma unroll
    for (int l = 0; l < L; l++) g_wsm[l * HW + hw] = a[l] * inv;
}

// ---------------- 5. xbar[c][hw] = sum_j w[j][hw] * x[j][c][hw] --------------
__global__ void xbar_kernel(const float* __restrict__ x) {
    const int hw    = blockIdx.x * 256 + threadIdx.x;
    const int cbase = blockIdx.y * 4;
    float w[L];
    #pragma unroll
    for (int j = 0; j < L; j++) w[j] = g_wsm[j * HW + hw];
    #pragma unroll
    for (int i = 0; i < 4; i++) {
        const int c = cbase + i;
        float acc = 0.f;
        #pragma unroll
        for (int j = 0; j < L; j++)
            acc += w[j] * x[(size_t)(j * C + c) * HW + hw];
        g_xbar[c * HW + hw] = acc;
    }
}

// ---------------- 6. out[f][c][hw] = Wv . xbar + bv, broadcast to 16 frames --
__global__ void gemm_out_kernel(const float* __restrict__ bv,
                                float* __restrict__ out) {
    __shared__ float wv_s[16][64];
    __shared__ float xb_s[16][64];
    const int tid = threadIdx.y * 16 + threadIdx.x;
    const int pG = blockIdx.x * 64;
    const int cG = blockIdx.y * 64;

    float acc[4][4];
    #pragma unroll
    for (int i = 0; i < 4; i++)
        #pragma unroll
        for (int j = 0; j < 4; j++) acc[i][j] = 0.f;

    for (int k0 = 0; k0 < C; k0 += 16) {
        #pragma unroll
        for (int i = tid; i < 1024; i += 256) {
            int r = i >> 6, col = i & 63;
            wv_s[r][col] = g_WvT[(k0 + r) * C + cG + col];
            xb_s[r][col] = g_xbar[(k0 + r) * HW + pG + col];
        }
        __syncthreads();
        #pragma unroll
        for (int kk = 0; kk < 16; kk++) {
            const float4 wv4 = *(const float4*)&wv_s[kk][threadIdx.y * 4];
            const float4 xb4 = *(const float4*)&xb_s[kk][threadIdx.x * 4];
            float wr[4] = {wv4.x, wv4.y, wv4.z, wv4.w};
            float xr[4] = {xb4.x, xb4.y, xb4.z, xb4.w};
            #pragma unroll
            for (int ci = 0; ci < 4; ci++)
                #pragma unroll
                for (int pi = 0; pi < 4; pi++)
                    acc[ci][pi] += wr[ci] * xr[pi];
        }
        __syncthreads();
    }

    const int c0 = cG + threadIdx.y * 4;
    const int p0 = pG + threadIdx.x * 4;
    #pragma unroll
    for (int ci = 0; ci < 4; ci++) {
        float b = bv[c0 + ci];
        float4 v = make_float4(acc[ci][0] + b, acc[ci][1] + b,
                               acc[ci][2] + b, acc[ci][3] + b);
        #pragma unroll
        for (int f = 0; f < L; f++)
            *(float4*)&out[(size_t)(f * C + c0 + ci) * HW + p0] = v;
    }
}

// ---------------- launch -----------------------------------------------------
extern "C" void kernel_launch(void* const* d_in, const int* in_sizes, int n_in,
                              void* d_out, int out_size) {
    const float* x  = (const float*)d_in[0];
    // d_in[1]=Wq, d_in[2]=bq unused (cancel in softmax over j)
    const float* Wk = (const float*)d_in[3];
    // d_in[4]=bk unused (border bias map is j-independent -> cancels)
    const float* Wv = (const float*)d_in[5];
    const float* bv = (const float*)d_in[6];
    const float* Wa = (const float*)d_in[7];
    // d_in[8]=ba unused (cancels)
    float* out = (float*)d_out;

    fold_kernel<<<25, 128>>>(Wk, Wa);
    transpose_wv<<<C, C>>>(Wv);
    proj_kernel<<<dim3(18, L), 256>>>(x);
    attn_weights_kernel<<<36, 256>>>();
    xbar_kernel<<<dim3(36, 32), 256>>>(x);
    gemm_out_kernel<<<dim3(HW / 64, 2), dim3(16, 16)>>>(bv, out);
}

// round 4
// speedup vs baseline: 2.8189x; 1.1690x over previous
#include <cuda_runtime.h>
#include <math.h>

#define L 16
#define C 128
#define HH 96
#define WW 96
#define HW (HH*WW)          // 9216
#define CHW (C*HW)          // 1179648

// ---------------- scratch (device globals; no runtime allocation) -------------
__device__ float2 g_weff2[C*25];       // [c][k] folded conv weights, duplicated {w,w}
__device__ float  g_WvT[C*C];          // WvT[k][c] = Wv[c][k]
__device__ float  g_t[25*L*HW];        // rank-25 projection [l][k][hw]  (14.7 MB)
__device__ float  g_Ak[L*HW];          // pre-softmax scores [j][hw]
__device__ float  g_wsm[L*HW];         // softmax weights [j][hw]
__device__ float  g_xbar[C*HW];        // weighted frame average [c][hw]

// ---------------- 1. fold Wk into the 25 per-tap projection vectors ----------
// weff[c][k] = sum_d Wa[C+d][k] * Wk[d][c]   (bk/ba/Wq/bq all cancel in softmax)
__global__ void fold_kernel(const float* __restrict__ Wk,
                            const float* __restrict__ Wa) {
    int k = blockIdx.x;      // 0..24
    int c = threadIdx.x;     // 0..127
    float acc = 0.f;
    #pragma unroll 4
    for (int d = 0; d < C; d++)
        acc += Wa[(C + d) * 25 + k] * Wk[d * C + c];
    g_weff2[c * 25 + k] = make_float2(acc, acc);
}

// ---------------- 2. transpose Wv -------------------------------------------
__global__ void transpose_wv(const float* __restrict__ Wv) {
    int k = blockIdx.x;
    int c = threadIdx.x;
    g_WvT[k * C + c] = Wv[c * C + k];
}

// ---------------- 3. t[l][k][hw] = sum_c weff[c][k] * x[l][c][hw] ------------
// grid (18, L), block 256. Each thread owns hw0 and hw0+256; the pair is packed
// into f32x2 so every tap costs one FFMA2. Weights broadcast from smem (LDS.64).
__global__ void proj_kernel(const float* __restrict__ x) {
    __shared__ unsigned long long ws2[C * 25];   // duplicated weights, 25.6 KB
    const int tid = threadIdx.x;
    const int l   = blockIdx.y;
    const int hw0 = blockIdx.x * 512 + tid;

    const unsigned long long* wsrc = (const unsigned long long*)g_weff2;
    #pragma unroll
    for (int i = tid; i < C * 25; i += 256) ws2[i] = wsrc[i];
    __syncthreads();

    unsigned long long acc[25];
    #pragma unroll
    for (int k = 0; k < 25; k++) acc[k] = 0ull;   // {0.f, 0.f}

    const float* xl = x + (size_t)l * CHW + hw0;
    #pragma unroll 2
    for (int c = 0; c < C; c++) {
        float a = xl[c * HW];
        float b = xl[c * HW + 256];
        unsigned long long av;
        asm("mov.b64 %0, {%1, %2};" : "=l"(av) : "f"(a), "f"(b));
        const unsigned long long* wc = &ws2[c * 25];
        #pragma unroll
        for (int k = 0; k < 25; k++)
            asm("fma.rn.f32x2 %0, %1, %2, %0;" : "+l"(acc[k]) : "l"(wc[k]), "l"(av));
    }

    float* tl = g_t + (size_t)l * 25 * HW + hw0;
    #pragma unroll
    for (int k = 0; k < 25; k++) {
        float lo, hi;
        asm("mov.b64 {%0, %1}, %2;" : "=f"(lo), "=f"(hi) : "l"(acc[k]));
        tl[k * HW]       = lo;
        tl[k * HW + 256] = hi;
    }
}

// ---------------- 4a. Ak[l][hw] = 25-tap shifted sum of t --------------------
// grid (36, 16) = 576 blocks -> full chip. 25 independent L2-hit loads/thread.
__global__ void ak_kernel() {
    const int l  = blockIdx.y;
    const int hw = blockIdx.x * 256 + threadIdx.x;
    const int h  = hw / WW;
    const int w  = hw - h * WW;

    const float* tl = g_t + (size_t)l * 25 * HW;
    float acc = 0.f;
    #pragma unroll
    for (int kh = 0; kh < 5; kh++) {
        const int hh = h + kh - 2;
        const bool hok = (unsigned)hh < HH;
        #pragma unroll
        for (int kw = 0; kw < 5; kw++) {
            const int ww = w + kw - 2;
            if (hok && (unsigned)ww < WW)
                acc += tl[(kh * 5 + kw) * HW + hh * WW + ww];
        }
    }
    g_Ak[l * HW + hw] = acc;
}

// ---------------- 4b. softmax over frames j per pixel -------------------------
__global__ void softmax_kernel() {
    const int hw = blockIdx.x * 256 + threadIdx.x;
    float a[L];
    float mx = -1e30f;
    #pragma unroll
    for (int j = 0; j < L; j++) {
        a[j] = g_Ak[j * HW + hw];
        mx = fmaxf(mx, a[j]);
    }
    float s = 0.f;
    #pragma unroll
    for (int j = 0; j < L; j++) { a[j] = __expf(a[j] - mx); s += a[j]; }
    float inv = 1.f / s;
    #pragma unroll
    for (int j = 0; j < L; j++) g_wsm[j * HW + hw] = a[j] * inv;
}

// ---------------- 5. xbar[c][hw] = sum_j w[j][hw] * x[j][c][hw] --------------
__global__ void xbar_kernel(const float* __restrict__ x) {
    const int hw    = blockIdx.x * 256 + threadIdx.x;
    const int cbase = blockIdx.y * 4;
    float w[L];
    #pragma unroll
    for (int j = 0; j < L; j++) w[j] = g_wsm[j * HW + hw];
    #pragma unroll
    for (int i = 0; i < 4; i++) {
        const int c = cbase + i;
        float acc = 0.f;
        #pragma unroll
        for (int j = 0; j < L; j++)
            acc += w[j] * x[(size_t)(j * C + c) * HW + hw];
        g_xbar[c * HW + hw] = acc;
    }
}

// ---------------- 6. out[f][c][hw] = Wv . xbar + bv, broadcast to 16 frames --
__global__ void gemm_out_kernel(const float* __restrict__ bv,
                                float* __restrict__ out) {
    __shared__ float wv_s[16][64];
    __shared__ float xb_s[16][64];
    const int tid = threadIdx.y * 16 + threadIdx.x;
    const int pG = blockIdx.x * 64;
    const int cG = blockIdx.y * 64;

    float acc[4][4];
    #pragma unroll
    for (int i = 0; i < 4; i++)
        #pragma unroll
        for (int j = 0; j < 4; j++) acc[i][j] = 0.f;

    for (int k0 = 0; k0 < C; k0 += 16) {
        #pragma unroll
        for (int i = tid; i < 1024; i += 256) {
            int r = i >> 6, col = i & 63;
            wv_s[r][col] = g_WvT[(k0 + r) * C + cG + col];
            xb_s[r][col] = g_xbar[(k0 + r) * HW + pG + col];
        }
        __syncthreads();
        #pragma unroll
        for (int kk = 0; kk < 16; kk++) {
            const float4 wv4 = *(const float4*)&wv_s[kk][threadIdx.y * 4];
            const float4 xb4 = *(const float4*)&xb_s[kk][threadIdx.x * 4];
            float wr[4] = {wv4.x, wv4.y, wv4.z, wv4.w};
            float xr[4] = {xb4.x, xb4.y, xb4.z, xb4.w};
            #pragma unroll
            for (int ci = 0; ci < 4; ci++)
                #pragma unroll
                for (int pi = 0; pi < 4; pi++)
                    acc[ci][pi] += wr[ci] * xr[pi];
        }
        __syncthreads();
    }

    const int c0 = cG + threadIdx.y * 4;
    const int p0 = pG + threadIdx.x * 4;
    #pragma unroll
    for (int ci = 0; ci < 4; ci++) {
        float b = bv[c0 + ci];
        float4 v = make_float4(acc[ci][0] + b, acc[ci][1] + b,
                               acc[ci][2] + b, acc[ci][3] + b);
        #pragma unroll
        for (int f = 0; f < L; f++)
            *(float4*)&out[(size_t)(f * C + c0 + ci) * HW + p0] = v;
    }
}

// ---------------- launch -----------------------------------------------------
extern "C" void kernel_launch(void* const* d_in, const int* in_sizes, int n_in,
                              void* d_out, int out_size) {
    const float* x  = (const float*)d_in[0];
    // d_in[1]=Wq, d_in[2]=bq unused (cancel in softmax over j)
    const float* Wk = (const float*)d_in[3];
    // d_in[4]=bk unused (border bias map is j-independent -> cancels)
    const float* Wv = (const float*)d_in[5];
    const float* bv = (const float*)d_in[6];
    const float* Wa = (const float*)d_in[7];
    // d_in[8]=ba unused (cancels)
    float* out = (float*)d_out;

    fold_kernel<<<25, 128>>>(Wk, Wa);
    transpose_wv<<<C, C>>>(Wv);
    proj_kernel<<<dim3(18, L), 256>>>(x);
    ak_kernel<<<dim3(36, L), 256>>>();
    softmax_kernel<<<36, 256>>>();
    xbar_kernel<<<dim3(36, 32), 256>>>(x);
    gemm_out_kernel<<<dim3(HW / 64, 2), dim3(16, 16)>>>(bv, out);
}

// round 6
// speedup vs baseline: 3.9111x; 1.3875x over previous
#include <cuda_runtime.h>
#include <math.h>

#define L 16
#define C 128
#define HH 96
#define WW 96
#define HW (HH*WW)          // 9216
#define CHW (C*HW)          // 1179648

typedef unsigned long long ull;

// ---------------- scratch (device globals; no runtime allocation) -------------
__device__ float2 g_weff2[C*25];       // [c][k] folded conv weights, duplicated {w,w}
__device__ float  g_WvT[C*C];          // WvT[k][c] = Wv[c][k]
__device__ float  g_t[25*L*HW];        // rank-25 projection [l][k][hw]  (14.7 MB)
__device__ float  g_Ak[L*HW];          // pre-softmax scores [j][hw]
__device__ float  g_xbar[C*HW];        // softmax-weighted frame average [c][hw]

// ---------------- 1. fold Wk into the 25 per-tap projection vectors ----------
// weff[c][k] = sum_d Wa[C+d][k] * Wk[d][c]   (bk/ba/Wq/bq all cancel in softmax)
__global__ void fold_kernel(const float* __restrict__ Wk,
                            const float* __restrict__ Wa) {
    int k = blockIdx.x;      // 0..24
    int c = threadIdx.x;     // 0..127
    float acc = 0.f;
    #pragma unroll 4
    for (int d = 0; d < C; d++)
        acc += Wa[(C + d) * 25 + k] * Wk[d * C + c];
    g_weff2[c * 25 + k] = make_float2(acc, acc);
}

// ---------------- 2. t[l][k][hw] = sum_c weff[c][k] * x[l][c][hw] ------------
// grid (9, L), block 512. Thread owns a consecutive pixel pair (float2 load),
// packed into f32x2 accumulators: one FFMA2 per tap.
__global__ void proj_kernel(const float* __restrict__ x) {
    __shared__ ull ws2[C * 25];   // duplicated weights, 25.6 KB
    const int tid = threadIdx.x;
    const int l   = blockIdx.y;
    const int hw0 = blockIdx.x * 1024 + tid * 2;

    const ull* wsrc = (const ull*)g_weff2;
    #pragma unroll
    for (int i = tid; i < C * 25; i += 512) ws2[i] = wsrc[i];
    __syncthreads();

    ull acc[25];
    #pragma unroll
    for (int k = 0; k < 25; k++) acc[k] = 0ull;

    const float2* xl = (const float2*)(x + (size_t)l * CHW + hw0);
    #pragma unroll 4
    for (int c = 0; c < C; c++) {
        float2 v = xl[c * (HW / 2)];
        ull av;
        asm("mov.b64 %0, {%1, %2};" : "=l"(av) : "f"(v.x), "f"(v.y));
        const ull* wc = &ws2[c * 25];
        #pragma unroll
        for (int k = 0; k < 25; k++)
            asm("fma.rn.f32x2 %0, %1, %2, %0;" : "+l"(acc[k]) : "l"(wc[k]), "l"(av));
    }

    float2* tl = (float2*)(g_t + (size_t)l * 25 * HW + hw0);
    #pragma unroll
    for (int k = 0; k < 25; k++) {
        float lo, hi;
        asm("mov.b64 {%0, %1}, %2;" : "=f"(lo), "=f"(hi) : "l"(acc[k]));
        tl[k * (HW / 2)] = make_float2(lo, hi);
    }
}

// ---------------- 3. Ak[l][hw] = 25-tap shifted sum of t ---------------------
__global__ void ak_kernel() {
    const int l  = blockIdx.y;
    const int hw = blockIdx.x * 256 + threadIdx.x;
    const int h  = hw / WW;
    const int w  = hw - h * WW;

    const float* tl = g_t + (size_t)l * 25 * HW;
    float acc = 0.f;
    #pragma unroll
    for (int kh = 0; kh < 5; kh++) {
        const int hh = h + kh - 2;
        const bool hok = (unsigned)hh < HH;
        #pragma unroll
        for (int kw = 0; kw < 5; kw++) {
            const int ww = w + kw - 2;
            if (hok && (unsigned)ww < WW)
                acc += tl[(kh * 5 + kw) * HW + hh * WW + ww];
        }
    }
    g_Ak[l * HW + hw] = acc;
}

// ---------------- 4. fused softmax + xbar ------------------------------------
// xbar[c][hw] = sum_j softmax_j(Ak)[j][hw] * x[j][c][hw]
// grid (9, 32), block 256; thread owns 4 consecutive pixels (float4) x 4 channels.
// Scale by 1/sum AFTER the j-reduction (one mul per output, not per term).
__global__ void xbarsm_kernel(const float* __restrict__ x) {
    const int p4    = blockIdx.x * 1024 + threadIdx.x * 4;   // pixel base
    const int cbase = blockIdx.y * 4;

    float4 a[L];
    #pragma unroll
    for (int j = 0; j < L; j++)
        a[j] = *(const float4*)&g_Ak[j * HW + p4];

    float4 mx = a[0];
    #pragma unroll
    for (int j = 1; j < L; j++) {
        mx.x = fmaxf(mx.x, a[j].x); mx.y = fmaxf(mx.y, a[j].y);
        mx.z = fmaxf(mx.z, a[j].z); mx.w = fmaxf(mx.w, a[j].w);
    }
    float4 s = make_float4(0.f, 0.f, 0.f, 0.f);
    #pragma unroll
    for (int j = 0; j < L; j++) {
        a[j].x = __expf(a[j].x - mx.x); s.x += a[j].x;
        a[j].y = __expf(a[j].y - mx.y); s.y += a[j].y;
        a[j].z = __expf(a[j].z - mx.z); s.z += a[j].z;
        a[j].w = __expf(a[j].w - mx.w); s.w += a[j].w;
    }
    const float4 inv = make_float4(1.f / s.x, 1.f / s.y, 1.f / s.z, 1.f / s.w);

    float4 acc[4];
    #pragma unroll
    for (int i = 0; i < 4; i++) acc[i] = make_float4(0.f, 0.f, 0.f, 0.f);

    #pragma unroll
    for (int j = 0; j < L; j++) {
        const float* xj = x + (size_t)(j * C + cbase) * HW + p4;
        #pragma unroll
        for (int i = 0; i < 4; i++) {
            const float4 xv = *(const float4*)&xj[i * HW];
            acc[i].x += a[j].x * xv.x;
            acc[i].y += a[j].y * xv.y;
            acc[i].z += a[j].z * xv.z;
            acc[i].w += a[j].w * xv.w;
        }
    }
    #pragma unroll
    for (int i = 0; i < 4; i++) {
        float4 r = make_float4(acc[i].x * inv.x, acc[i].y * inv.y,
                               acc[i].z * inv.z, acc[i].w * inv.w);
        *(float4*)&g_xbar[(cbase + i) * HW + p4] = r;
    }
}

// ---------------- 5. transpose Wv --------------------------------------------
__global__ void transpose_wv(const float* __restrict__ Wv) {
    int k = blockIdx.x;
    int c = threadIdx.x;
    g_WvT[k * C + c] = Wv[c * C + k];
}

// ---------------- 6. out[f][c][hw] = Wv . xbar + bv, broadcast to 16 frames --
__global__ void gemm_out_kernel(const float* __restrict__ bv,
                                float* __restrict__ out) {
    __shared__ float wv_s[16][64];
    __shared__ float xb_s[16][64];
    const int tid = threadIdx.y * 16 + threadIdx.x;
    const int pG = blockIdx.x * 64;
    const int cG = blockIdx.y * 64;

    const int sr   = tid >> 4;          // 0..15
    const int sc4  = (tid & 15) * 4;    // 0..60

    float acc[4][4];
    #pragma unroll
    for (int i = 0; i < 4; i++)
        #pragma unroll
        for (int j = 0; j < 4; j++) acc[i][j] = 0.f;

    for (int k0 = 0; k0 < C; k0 += 16) {
        *(float4*)&wv_s[sr][sc4] = *(const float4*)&g_WvT[(k0 + sr) * C + cG + sc4];
        *(float4*)&xb_s[sr][sc4] = *(const float4*)&g_xbar[(k0 + sr) * HW + pG + sc4];
        __syncthreads();
        #pragma unroll
        for (int kk = 0; kk < 16; kk++) {
            const float4 wv4 = *(const float4*)&wv_s[kk][threadIdx.y * 4];
            const float4 xb4 = *(const float4*)&xb_s[kk][threadIdx.x * 4];
            float wr[4] = {wv4.x, wv4.y, wv4.z, wv4.w};
            float xr[4] = {xb4.x, xb4.y, xb4.z, xb4.w};
            #pragma unroll
            for (int ci = 0; ci < 4; ci++)
                #pragma unroll
                for (int pi = 0; pi < 4; pi++)
                    acc[ci][pi] += wr[ci] * xr[pi];
        }
        __syncthreads();
    }

    const int c0 = cG + threadIdx.y * 4;
    const int p0 = pG + threadIdx.x * 4;
    #pragma unroll
    for (int ci = 0; ci < 4; ci++) {
        float b = bv[c0 + ci];
        float4 v = make_float4(acc[ci][0] + b, acc[ci][1] + b,
                               acc[ci][2] + b, acc[ci][3] + b);
        #pragma unroll
        for (int f = 0; f < L; f++)
            *(float4*)&out[(size_t)(f * C + c0 + ci) * HW + p0] = v;
    }
}

// ---------------- launch -----------------------------------------------------
extern "C" void kernel_launch(void* const* d_in, const int* in_sizes, int n_in,
                              void* d_out, int out_size) {
    const float* x  = (const float*)d_in[0];
    // d_in[1]=Wq, d_in[2]=bq unused (cancel in softmax over j)
    const float* Wk = (const float*)d_in[3];
    // d_in[4]=bk unused (border bias map is j-independent -> cancels)
    const float* Wv = (const float*)d_in[5];
    const float* bv = (const float*)d_in[6];
    const float* Wa = (const float*)d_in[7];
    // d_in[8]=ba unused (cancels)
    float* out = (float*)d_out;

    // order chosen so the single ncu capture (launch index 3) profiles xbarsm
    fold_kernel<<<25, 128>>>(Wk, Wa);                     // 0
    proj_kernel<<<dim3(9, L), 512>>>(x);                  // 1
    ak_kernel<<<dim3(36, L), 256>>>();                    // 2
    xbarsm_kernel<<<dim3(9, 32), 256>>>(x);               // 3  <- profiled
    transpose_wv<<<C, C>>>(Wv);                           // 4
    gemm_out_kernel<<<dim3(HW / 64, 2), dim3(16, 16)>>>(bv, out);  // 5
}